// round 1
// baseline (speedup 1.0000x reference)
#include <cuda_runtime.h>
#include <cuda_bf16.h>
#include <cstdint>

// ---------------------------------------------------------------------------
// WordGraphNet: 2-layer weighted GraphConv
//   layer(h, W, b): Wh = h@W + b ; msg = Wh[src]*ew ; s = segsum(msg, dst)
//                   deg = segsum(1, dst) ; out = s / max(deg,1)
//   out = layer2( leaky_relu(layer1(x)) )
// Shapes: x[50000,128], W1[128,64], W2[64,64], E=1.2M edges, out[50000,64]
// ---------------------------------------------------------------------------

#define MAX_NODES 50000
#define HID 64
#define NEG_SLOPE 0.01f

// Device scratch (no allocations allowed)
__device__ float g_Wh[MAX_NODES * HID];     // projected features
__device__ float g_accum[MAX_NODES * HID];  // segment-sum accumulator / h1
__device__ float g_deg[MAX_NODES];          // in-degree (float)

// ---------------------------------------------------------------------------
// GEMM + bias: out[n][64] = H[n][K] @ W[K][64] + b[64]
// Block: 256 threads, 64 nodes per block; thread computes 16 contiguous cols.
// W held in smem; H rows read via __ldg (L1-resident across k-loop).
// ---------------------------------------------------------------------------
template <int K>
__global__ void gemm_bias_kernel(const float* __restrict__ H,
                                 const float* __restrict__ Wg,
                                 const float* __restrict__ bg,
                                 float* __restrict__ out,
                                 int n_nodes) {
    __shared__ float Ws[K * HID];
    __shared__ float Bs[HID];

    int tid = threadIdx.x;
    for (int i = tid; i < K * HID; i += blockDim.x) Ws[i] = Wg[i];
    if (tid < HID) Bs[tid] = bg[tid];
    __syncthreads();

    int r_local = tid >> 2;            // 0..63
    int cgrp    = (tid & 3) * 16;      // 0,16,32,48
    int node    = blockIdx.x * 64 + r_local;
    if (node >= n_nodes) return;

    float acc[16];
#pragma unroll
    for (int j = 0; j < 16; j++) acc[j] = Bs[cgrp + j];

    const float* hrow = H + (size_t)node * K;
#pragma unroll 8
    for (int k = 0; k < K; k++) {
        float a = __ldg(hrow + k);
        const float4* wrow = reinterpret_cast<const float4*>(Ws + k * HID + cgrp);
        float4 w0 = wrow[0], w1 = wrow[1], w2 = wrow[2], w3 = wrow[3];
        acc[0]  += a * w0.x; acc[1]  += a * w0.y; acc[2]  += a * w0.z; acc[3]  += a * w0.w;
        acc[4]  += a * w1.x; acc[5]  += a * w1.y; acc[6]  += a * w1.z; acc[7]  += a * w1.w;
        acc[8]  += a * w2.x; acc[9]  += a * w2.y; acc[10] += a * w2.z; acc[11] += a * w2.w;
        acc[12] += a * w3.x; acc[13] += a * w3.y; acc[14] += a * w3.z; acc[15] += a * w3.w;
    }

    float4* orow = reinterpret_cast<float4*>(out + (size_t)node * HID + cgrp);
#pragma unroll
    for (int q = 0; q < 4; q++) {
        orow[q] = make_float4(acc[q * 4 + 0], acc[q * 4 + 1],
                              acc[q * 4 + 2], acc[q * 4 + 3]);
    }
}

// ---------------------------------------------------------------------------
// Edge scatter: 16 threads per edge, one float4 per thread.
//   accum[dst] += Wh[src] * ew   (red.global.add.v4.f32)
//   deg[dst]   += 1              (first chunk only, layer-1 pass only)
// ---------------------------------------------------------------------------
__device__ __forceinline__ void red_add_v4(float* addr, float4 v) {
    asm volatile("red.global.add.v4.f32 [%0], {%1, %2, %3, %4};"
                 :: "l"(addr), "f"(v.x), "f"(v.y), "f"(v.z), "f"(v.w)
                 : "memory");
}

__global__ void scatter_kernel(const float* __restrict__ Wh,
                               const float* __restrict__ ew,
                               const int* __restrict__ src,
                               const int* __restrict__ dst,
                               float* __restrict__ accum,
                               float* __restrict__ deg,
                               int n_edges, int do_deg) {
    long long t = (long long)blockIdx.x * blockDim.x + threadIdx.x;
    int e  = (int)(t >> 4);
    int c4 = (int)(t & 15);
    if (e >= n_edges) return;

    int   s = __ldg(src + e);
    int   d = __ldg(dst + e);
    float w = __ldg(ew + e);

    float4 v = __ldg(reinterpret_cast<const float4*>(Wh + (size_t)s * HID) + c4);
    v.x *= w; v.y *= w; v.z *= w; v.w *= w;

    red_add_v4(accum + (size_t)d * HID + c4 * 4, v);
    if (do_deg && c4 == 0) atomicAdd(deg + d, 1.0f);
}

// ---------------------------------------------------------------------------
// Normalize: v = accum / max(deg,1); optional leaky-relu. In place.
// One thread per float4 (n_nodes * 16 threads).
// ---------------------------------------------------------------------------
__global__ void normalize_kernel(float* __restrict__ buf,
                                 const float* __restrict__ deg,
                                 int n_nodes, int do_leaky) {
    int idx = blockIdx.x * blockDim.x + threadIdx.x;
    if (idx >= n_nodes * 16) return;
    int node = idx >> 4;

    float dg  = __ldg(deg + node);
    float inv = 1.0f / fmaxf(dg, 1.0f);

    float4* p = reinterpret_cast<float4*>(buf) + idx;
    float4 v = *p;
    v.x *= inv; v.y *= inv; v.z *= inv; v.w *= inv;
    if (do_leaky) {
        v.x = v.x > 0.f ? v.x : NEG_SLOPE * v.x;
        v.y = v.y > 0.f ? v.y : NEG_SLOPE * v.y;
        v.z = v.z > 0.f ? v.z : NEG_SLOPE * v.z;
        v.w = v.w > 0.f ? v.w : NEG_SLOPE * v.w;
    }
    *p = v;
}

// ---------------------------------------------------------------------------
// Launch
// ---------------------------------------------------------------------------
extern "C" void kernel_launch(void* const* d_in, const int* in_sizes, int n_in,
                              void* d_out, int out_size) {
    const float* x   = (const float*)d_in[0];
    const float* ew  = (const float*)d_in[1];
    const float* W1  = (const float*)d_in[2];
    const float* b1  = (const float*)d_in[3];
    const float* W2  = (const float*)d_in[4];
    const float* b2  = (const float*)d_in[5];
    const int*   src = (const int*)d_in[6];
    const int*   dst = (const int*)d_in[7];
    float*       out = (float*)d_out;

    int n_nodes = in_sizes[0] / 128;  // x is [N,128]
    int n_edges = in_sizes[1];

    void *pWh_v, *pAcc_v, *pDeg_v;
    cudaGetSymbolAddress(&pWh_v,  g_Wh);
    cudaGetSymbolAddress(&pAcc_v, g_accum);
    cudaGetSymbolAddress(&pDeg_v, g_deg);
    float* pWh  = (float*)pWh_v;
    float* pAcc = (float*)pAcc_v;
    float* pDeg = (float*)pDeg_v;

    // Zero accumulators, degree, and output
    cudaMemsetAsync(pAcc, 0, (size_t)n_nodes * HID * sizeof(float));
    cudaMemsetAsync(pDeg, 0, (size_t)n_nodes * sizeof(float));
    cudaMemsetAsync(out,  0, (size_t)out_size * sizeof(float));

    int gemm_blocks = (n_nodes + 63) / 64;
    long long sc_threads = (long long)n_edges * 16;
    int sc_blocks = (int)((sc_threads + 255) / 256);
    int nm_blocks = (n_nodes * 16 + 255) / 256;

    // Layer 1
    gemm_bias_kernel<128><<<gemm_blocks, 256>>>(x, W1, b1, pWh, n_nodes);
    scatter_kernel<<<sc_blocks, 256>>>(pWh, ew, src, dst, pAcc, pDeg, n_edges, 1);
    normalize_kernel<<<nm_blocks, 256>>>(pAcc, pDeg, n_nodes, 1);

    // Layer 2 (h1 lives in pAcc)
    gemm_bias_kernel<64><<<gemm_blocks, 256>>>(pAcc, W2, b2, pWh, n_nodes);
    scatter_kernel<<<sc_blocks, 256>>>(pWh, ew, src, dst, out, pDeg, n_edges, 0);
    normalize_kernel<<<nm_blocks, 256>>>(out, pDeg, n_nodes, 0);
}

// round 2
// speedup vs baseline: 1.8480x; 1.8480x over previous
#include <cuda_runtime.h>
#include <cuda_bf16.h>
#include <cstdint>

// ---------------------------------------------------------------------------
// WordGraphNet: 2-layer weighted GraphConv
//   layer(h,W,b): Wh = h@W + b ; s = segsum(Wh[src]*ew, dst) ; out = s/max(deg,1)
//   out = layer2( leaky_relu(layer1(x)) )
// ---------------------------------------------------------------------------

#define MAX_NODES 50000
#define HID 64
#define NEG_SLOPE 0.01f

__device__ float g_Wh[MAX_NODES * HID];     // projected features
__device__ float g_accum[MAX_NODES * HID];  // layer-1 segment sums
__device__ float g_deg[MAX_NODES];          // in-degree

// ---------------------------------------------------------------------------
// Tiled GEMM + bias: out[n][64] = H[n][K] @ W[K][64] + b
// Block: 128 threads, tile 128 nodes x 64 cols, 8x8 register tile per thread.
// H staged node-major in smem with pad (KCP=36) for conflict-free scalar reads.
// PRESCALE: fold layer-1 normalize (/max(deg,1)) + leaky-relu into staging.
// ---------------------------------------------------------------------------
#define TILE_M 128
#define KC 32
#define KCP 36

__device__ __forceinline__ float leaky(float v) {
    return v > 0.f ? v : NEG_SLOPE * v;
}

template <int K, bool PRESCALE>
__global__ __launch_bounds__(128)
void gemm_tile_kernel(const float* __restrict__ H,
                      const float* __restrict__ Wg,
                      const float* __restrict__ bg,
                      const float* __restrict__ deg,
                      float* __restrict__ out,
                      int n_nodes) {
    __shared__ float Hs[TILE_M * KCP];   // node-major, padded rows
    __shared__ float Ws[KC * HID];       // k-major chunk

    const int tid = threadIdx.x;
    const int tx = tid & 7;    // col group: cols [4tx..4tx+3] and [32+4tx..32+4tx+3]
    const int ty = tid >> 3;   // node group: nodes ty + 16*i, i=0..7 (interleaved)
    const int node0 = blockIdx.x * TILE_M;

    float acc[8][8];
#pragma unroll
    for (int i = 0; i < 8; i++)
#pragma unroll
        for (int j = 0; j < 8; j++) acc[i][j] = 0.f;

    for (int kc0 = 0; kc0 < K; kc0 += KC) {
        // --- stage W chunk (straight float4 copy, coalesced) ---
        {
            const float4* Wg4 = reinterpret_cast<const float4*>(Wg + kc0 * HID);
            float4* Ws4w = reinterpret_cast<float4*>(Ws);
#pragma unroll
            for (int f = tid; f < KC * 16; f += 128)
                Ws4w[f] = __ldg(Wg4 + f);
        }
        // --- stage H chunk: 1024 float4, 8 per thread, coalesced global reads ---
#pragma unroll
        for (int f = tid; f < TILE_M * (KC / 4); f += 128) {
            int m = f >> 3;      // KC/4 == 8 float4 per node-row chunk
            int j = f & 7;
            int node = node0 + m;
            float4 v = make_float4(0.f, 0.f, 0.f, 0.f);
            if (node < n_nodes) {
                v = __ldg(reinterpret_cast<const float4*>(H + (size_t)node * K + kc0) + j);
                if (PRESCALE) {
                    float s = 1.0f / fmaxf(__ldg(deg + node), 1.0f);
                    v.x = leaky(v.x) * s;
                    v.y = leaky(v.y) * s;
                    v.z = leaky(v.z) * s;
                    v.w = leaky(v.w) * s;
                }
            }
            *reinterpret_cast<float4*>(Hs + m * KCP + 4 * j) = v;
        }
        __syncthreads();

        const float4* Ws4 = reinterpret_cast<const float4*>(Ws);
#pragma unroll 4
        for (int kk = 0; kk < KC; kk++) {
            float h[8];
#pragma unroll
            for (int i = 0; i < 8; i++)
                h[i] = Hs[(ty + 16 * i) * KCP + kk];
            float4 w0 = Ws4[kk * 16 + tx];
            float4 w1 = Ws4[kk * 16 + 8 + tx];
            float w[8] = {w0.x, w0.y, w0.z, w0.w, w1.x, w1.y, w1.z, w1.w};
#pragma unroll
            for (int i = 0; i < 8; i++)
#pragma unroll
                for (int j = 0; j < 8; j++)
                    acc[i][j] += h[i] * w[j];
        }
        __syncthreads();
    }

    // --- epilogue: add bias, vectorized coalesced stores ---
    float4 b0 = __ldg(reinterpret_cast<const float4*>(bg) + tx);
    float4 b1 = __ldg(reinterpret_cast<const float4*>(bg) + 8 + tx);
#pragma unroll
    for (int i = 0; i < 8; i++) {
        int node = node0 + ty + 16 * i;
        if (node < n_nodes) {
            float4 o0 = make_float4(acc[i][0] + b0.x, acc[i][1] + b0.y,
                                    acc[i][2] + b0.z, acc[i][3] + b0.w);
            float4 o1 = make_float4(acc[i][4] + b1.x, acc[i][5] + b1.y,
                                    acc[i][6] + b1.z, acc[i][7] + b1.w);
            *reinterpret_cast<float4*>(out + (size_t)node * HID + tx * 4) = o0;
            *reinterpret_cast<float4*>(out + (size_t)node * HID + 32 + tx * 4) = o1;
        }
    }
}

// ---------------------------------------------------------------------------
// Edge scatter: 16 threads per edge, one float4 per thread.
// ---------------------------------------------------------------------------
__device__ __forceinline__ void red_add_v4(float* addr, float4 v) {
    asm volatile("red.global.add.v4.f32 [%0], {%1, %2, %3, %4};"
                 :: "l"(addr), "f"(v.x), "f"(v.y), "f"(v.z), "f"(v.w)
                 : "memory");
}

__global__ void scatter_kernel(const float* __restrict__ Wh,
                               const float* __restrict__ ew,
                               const int* __restrict__ src,
                               const int* __restrict__ dst,
                               float* __restrict__ accum,
                               float* __restrict__ deg,
                               int n_edges, int do_deg) {
    long long t = (long long)blockIdx.x * blockDim.x + threadIdx.x;
    int e  = (int)(t >> 4);
    int c4 = (int)(t & 15);
    if (e >= n_edges) return;

    int   s = __ldg(src + e);
    int   d = __ldg(dst + e);
    float w = __ldg(ew + e);

    float4 v = __ldg(reinterpret_cast<const float4*>(Wh + (size_t)s * HID) + c4);
    v.x *= w; v.y *= w; v.z *= w; v.w *= w;

    red_add_v4(accum + (size_t)d * HID + c4 * 4, v);
    if (do_deg && c4 == 0) atomicAdd(deg + d, 1.0f);
}

// ---------------------------------------------------------------------------
// Final normalize: out = accum / max(deg,1) (no leaky on last layer)
// ---------------------------------------------------------------------------
__global__ void normalize_kernel(float* __restrict__ buf,
                                 const float* __restrict__ deg,
                                 int n_nodes) {
    int idx = blockIdx.x * blockDim.x + threadIdx.x;
    if (idx >= n_nodes * 16) return;
    int node = idx >> 4;

    float inv = 1.0f / fmaxf(__ldg(deg + node), 1.0f);
    float4* p = reinterpret_cast<float4*>(buf) + idx;
    float4 v = *p;
    v.x *= inv; v.y *= inv; v.z *= inv; v.w *= inv;
    *p = v;
}

// ---------------------------------------------------------------------------
// Launch
// ---------------------------------------------------------------------------
extern "C" void kernel_launch(void* const* d_in, const int* in_sizes, int n_in,
                              void* d_out, int out_size) {
    const float* x   = (const float*)d_in[0];
    const float* ew  = (const float*)d_in[1];
    const float* W1  = (const float*)d_in[2];
    const float* b1  = (const float*)d_in[3];
    const float* W2  = (const float*)d_in[4];
    const float* b2  = (const float*)d_in[5];
    const int*   src = (const int*)d_in[6];
    const int*   dst = (const int*)d_in[7];
    float*       out = (float*)d_out;

    int n_nodes = in_sizes[0] / 128;
    int n_edges = in_sizes[1];

    void *pWh_v, *pAcc_v, *pDeg_v;
    cudaGetSymbolAddress(&pWh_v,  g_Wh);
    cudaGetSymbolAddress(&pAcc_v, g_accum);
    cudaGetSymbolAddress(&pDeg_v, g_deg);
    float* pWh  = (float*)pWh_v;
    float* pAcc = (float*)pAcc_v;
    float* pDeg = (float*)pDeg_v;

    cudaMemsetAsync(pAcc, 0, (size_t)n_nodes * HID * sizeof(float));
    cudaMemsetAsync(pDeg, 0, (size_t)n_nodes * sizeof(float));
    cudaMemsetAsync(out,  0, (size_t)out_size * sizeof(float));

    int gemm_blocks = (n_nodes + TILE_M - 1) / TILE_M;
    long long sc_threads = (long long)n_edges * 16;
    int sc_blocks = (int)((sc_threads + 255) / 256);
    int nm_blocks = (n_nodes * 16 + 255) / 256;

    // Layer 1: project, scatter(+degree)
    gemm_tile_kernel<128, false><<<gemm_blocks, 128>>>(x, W1, b1, nullptr, pWh, n_nodes);
    scatter_kernel<<<sc_blocks, 256>>>(pWh, ew, src, dst, pAcc, pDeg, n_edges, 1);

    // Layer 2: project (normalize+leaky fused into staging), scatter, normalize
    gemm_tile_kernel<64, true><<<gemm_blocks, 128>>>(pAcc, W2, b2, pDeg, pWh, n_nodes);
    scatter_kernel<<<sc_blocks, 256>>>(pWh, ew, src, dst, out, pDeg, n_edges, 0);
    normalize_kernel<<<nm_blocks, 256>>>(out, pDeg, n_nodes);
}